// round 1
// baseline (speedup 1.0000x reference)
#include <cuda_runtime.h>
#include <math.h>

#define BB 4
#define SS 4096
#define HH 1024
#define FF 4096
#define EE 8
#define TOPK 2
#define NTOK (BB*SS)        // 16384 tokens
#define NSLOT (NTOK*TOPK)   // 32768 (token,expert) slots

// ---------------- scratch (static device globals; no runtime allocation) ----
__device__ int   g_counts[EE];
__device__ int   g_offsets[EE];
__device__ int   g_tlist[EE*NTOK];
__device__ float g_glist[EE*NTOK];
__device__ float g_hdd[(size_t)NSLOT * FF];   // 536 MB fp32 intermediate

// ---------------- helpers ---------------------------------------------------
__device__ __forceinline__ float gelu_tanh(float v) {
    // exact JAX approximate-gelu formula (default approximate=True)
    const float c = 0.7978845608028654f;   // sqrt(2/pi)
    float t = tanhf(c * (v + 0.044715f * v * v * v));
    return 0.5f * v * (1.0f + t);
}

// ---------------- kernel 1: zero counts + output ----------------------------
__global__ void zero_kernel(float* __restrict__ out) {
    int idx = blockIdx.x * blockDim.x + threadIdx.x;
    if (idx < EE) g_counts[idx] = 0;
    size_t total = (size_t)NTOK * HH;
    size_t stride = (size_t)gridDim.x * blockDim.x;
    for (size_t i = idx; i < total; i += stride) out[i] = 0.0f;
}

// ---------------- kernel 2: router (warp per token) -------------------------
__global__ __launch_bounds__(256) void router_kernel(
    const float* __restrict__ x, const float* __restrict__ Wg)
{
    int warp = threadIdx.x >> 5;
    int lane = threadIdx.x & 31;
    int token = blockIdx.x * 8 + warp;
    if (token >= NTOK) return;

    const float* xr = x + (size_t)token * HH;
    float acc[EE];
#pragma unroll
    for (int e = 0; e < EE; e++) acc[e] = 0.0f;

    for (int k = lane; k < HH; k += 32) {
        float xv = xr[k];
        const float* wr = Wg + (size_t)k * EE;
        float4 w0 = *(const float4*)(wr);
        float4 w1 = *(const float4*)(wr + 4);
        acc[0] += xv * w0.x; acc[1] += xv * w0.y;
        acc[2] += xv * w0.z; acc[3] += xv * w0.w;
        acc[4] += xv * w1.x; acc[5] += xv * w1.y;
        acc[6] += xv * w1.z; acc[7] += xv * w1.w;
    }
#pragma unroll
    for (int off = 16; off > 0; off >>= 1) {
#pragma unroll
        for (int e = 0; e < EE; e++)
            acc[e] += __shfl_xor_sync(0xFFFFFFFFu, acc[e], off);
    }

    if (lane == 0) {
        int i0 = 0;
#pragma unroll
        for (int e = 1; e < EE; e++) if (acc[e] > acc[i0]) i0 = e;
        int i1 = (i0 == 0) ? 1 : 0;
#pragma unroll
        for (int e = 0; e < EE; e++)
            if (e != i0 && acc[e] > acc[i1]) i1 = e;

        float m  = acc[i0];
        float p1 = __expf(acc[i1] - m);   // fine: |diff| bounded, expf tol ok
        p1 = expf(acc[i1] - m);           // use accurate expf for safety
        float denom = 1.0f + p1;
        float w0 = 1.0f / denom;
        float w1 = p1 / denom;

        int p = atomicAdd(&g_counts[i0], 1);
        g_tlist[i0 * NTOK + p] = token;
        g_glist[i0 * NTOK + p] = w0;
        p = atomicAdd(&g_counts[i1], 1);
        g_tlist[i1 * NTOK + p] = token;
        g_glist[i1 * NTOK + p] = w1;
    }
}

// ---------------- kernel 3: exclusive prefix over 8 counts -------------------
__global__ void offsets_kernel() {
    if (threadIdx.x == 0 && blockIdx.x == 0) {
        int s = 0;
        for (int e = 0; e < EE; e++) { g_offsets[e] = s; s += g_counts[e]; }
    }
}

// ---------------- GEMM tile config ------------------------------------------
// 128x128 tile, BK=8, 256 threads, 8x8 per-thread micro-tile.

// kernel 4: hdd[slot, :] = gelu( x[token,:] @ W1[e] + b1[e] )
__global__ __launch_bounds__(256) void gemm1_kernel(
    const float* __restrict__ x, const float* __restrict__ W1,
    const float* __restrict__ b1)
{
    const int e = blockIdx.z;
    const int count = g_counts[e];
    const int mtile = blockIdx.y * 128;
    if (mtile >= count) return;
    const int off = g_offsets[e];
    const int ntile = blockIdx.x * 128;
    const float* Bmat = W1 + (size_t)e * HH * FF;

    __shared__ float As[8][128];
    __shared__ float Bs[8][128];

    const int t = threadIdx.x;
    const int arow  = t >> 1;
    const int acol4 = (t & 1) * 4;
    const int brow  = t >> 5;
    const int bcol4 = (t & 31) * 4;
    const int tx = t & 15, ty = t >> 4;

    int m_a = mtile + arow;
    int tok = -1;
    if (m_a < count) tok = g_tlist[e * NTOK + m_a];
    const float* xrow = (tok >= 0) ? (x + (size_t)tok * HH) : x;

    float acc[8][8];
#pragma unroll
    for (int i = 0; i < 8; i++)
#pragma unroll
        for (int j = 0; j < 8; j++) acc[i][j] = 0.0f;

    for (int k0 = 0; k0 < HH; k0 += 8) {
        float4 av = make_float4(0.f, 0.f, 0.f, 0.f);
        if (tok >= 0) av = *(const float4*)(xrow + k0 + acol4);
        float4 bv = *(const float4*)(Bmat + (size_t)(k0 + brow) * FF + ntile + bcol4);
        __syncthreads();
        As[acol4 + 0][arow] = av.x;
        As[acol4 + 1][arow] = av.y;
        As[acol4 + 2][arow] = av.z;
        As[acol4 + 3][arow] = av.w;
        *(float4*)&Bs[brow][bcol4] = bv;
        __syncthreads();

#pragma unroll
        for (int kk = 0; kk < 8; kk++) {
            float a[8], b[8];
            *(float4*)(a)     = *(const float4*)&As[kk][ty * 8];
            *(float4*)(a + 4) = *(const float4*)&As[kk][ty * 8 + 4];
            *(float4*)(b)     = *(const float4*)&Bs[kk][tx * 8];
            *(float4*)(b + 4) = *(const float4*)&Bs[kk][tx * 8 + 4];
#pragma unroll
            for (int i = 0; i < 8; i++)
#pragma unroll
                for (int j = 0; j < 8; j++)
                    acc[i][j] += a[i] * b[j];
        }
    }

    const int ncol = ntile + tx * 8;
    float bias[8];
#pragma unroll
    for (int j = 0; j < 8; j++) bias[j] = b1[(size_t)e * FF + ncol + j];

#pragma unroll
    for (int i = 0; i < 8; i++) {
        int m = mtile + ty * 8 + i;
        if (m < count) {
            float v[8];
#pragma unroll
            for (int j = 0; j < 8; j++) v[j] = gelu_tanh(acc[i][j] + bias[j]);
            float* dst = g_hdd + (size_t)(off + m) * FF + ncol;
            *(float4*)(dst)     = *(float4*)(v);
            *(float4*)(dst + 4) = *(float4*)(v + 4);
        }
    }
}

// kernel 5: out[token,:] += gate * ( hdd[slot,:] @ W2[e] + b2[e] )
__global__ __launch_bounds__(256) void gemm2_kernel(
    const float* __restrict__ W2, const float* __restrict__ b2,
    float* __restrict__ out)
{
    const int e = blockIdx.z;
    const int count = g_counts[e];
    const int mtile = blockIdx.y * 128;
    if (mtile >= count) return;
    const int off = g_offsets[e];
    const int ntile = blockIdx.x * 128;
    const float* Bmat = W2 + (size_t)e * FF * HH;

    __shared__ float As[8][128];
    __shared__ float Bs[8][128];

    const int t = threadIdx.x;
    const int arow  = t >> 1;
    const int acol4 = (t & 1) * 4;
    const int brow  = t >> 5;
    const int bcol4 = (t & 31) * 4;
    const int tx = t & 15, ty = t >> 4;

    const int m_a = mtile + arow;
    const bool avalid = (m_a < count);
    const float* arowp = g_hdd + (size_t)(off + (avalid ? m_a : 0)) * FF;

    float acc[8][8];
#pragma unroll
    for (int i = 0; i < 8; i++)
#pragma unroll
        for (int j = 0; j < 8; j++) acc[i][j] = 0.0f;

    for (int k0 = 0; k0 < FF; k0 += 8) {
        float4 av = make_float4(0.f, 0.f, 0.f, 0.f);
        if (avalid) av = *(const float4*)(arowp + k0 + acol4);
        float4 bv = *(const float4*)(Bmat + (size_t)(k0 + brow) * HH + ntile + bcol4);
        __syncthreads();
        As[acol4 + 0][arow] = av.x;
        As[acol4 + 1][arow] = av.y;
        As[acol4 + 2][arow] = av.z;
        As[acol4 + 3][arow] = av.w;
        *(float4*)&Bs[brow][bcol4] = bv;
        __syncthreads();

#pragma unroll
        for (int kk = 0; kk < 8; kk++) {
            float a[8], b[8];
            *(float4*)(a)     = *(const float4*)&As[kk][ty * 8];
            *(float4*)(a + 4) = *(const float4*)&As[kk][ty * 8 + 4];
            *(float4*)(b)     = *(const float4*)&Bs[kk][tx * 8];
            *(float4*)(b + 4) = *(const float4*)&Bs[kk][tx * 8 + 4];
#pragma unroll
            for (int i = 0; i < 8; i++)
#pragma unroll
                for (int j = 0; j < 8; j++)
                    acc[i][j] += a[i] * b[j];
        }
    }

    const int ncol = ntile + tx * 8;
    float bias[8];
#pragma unroll
    for (int j = 0; j < 8; j++) bias[j] = b2[(size_t)e * HH + ncol + j];

#pragma unroll
    for (int i = 0; i < 8; i++) {
        int m = mtile + ty * 8 + i;
        if (m < count) {
            int   tok = g_tlist[e * NTOK + m];
            float g   = g_glist[e * NTOK + m];
            float* dst = out + (size_t)tok * HH + ncol;
#pragma unroll
            for (int j = 0; j < 8; j++)
                atomicAdd(dst + j, g * (acc[i][j] + bias[j]));
        }
    }
}

// ---------------- launcher ---------------------------------------------------
extern "C" void kernel_launch(void* const* d_in, const int* in_sizes, int n_in,
                              void* d_out, int out_size)
{
    const float* x  = (const float*)d_in[0];
    const float* Wg = (const float*)d_in[1];
    const float* W1 = (const float*)d_in[2];
    const float* b1 = (const float*)d_in[3];
    const float* W2 = (const float*)d_in[4];
    const float* b2 = (const float*)d_in[5];
    float* out = (float*)d_out;

    zero_kernel<<<512, 256>>>(out);
    router_kernel<<<NTOK / 8, 256>>>(x, Wg);
    offsets_kernel<<<1, 32>>>();
    gemm1_kernel<<<dim3(FF / 128, NTOK / 128, EE), 256>>>(x, W1, b1);
    gemm2_kernel<<<dim3(HH / 128, NTOK / 128, EE), 256>>>(W2, b2, out);
}

// round 3
// speedup vs baseline: 1.8224x; 1.8224x over previous
#include <cuda_runtime.h>
#include <cstdint>
#include <math.h>

#define BB 4
#define SS 4096
#define HH 1024
#define FF 4096
#define EE 8
#define NTOK (BB*SS)        // 16384
#define NSLOT (NTOK*2)      // 32768

// ---------------- scratch ----------------------------------------------------
__device__ int   g_counts[EE];
__device__ int   g_offsets[EE];
__device__ int   g_tlist[EE*NTOK];
__device__ float g_glist[EE*NTOK];
__device__ float g_hdd[(size_t)NSLOT * FF];   // 536 MB fp32 intermediate

// ---------------- helpers -----------------------------------------------------
__device__ __forceinline__ uint32_t smem_u32(const void* p) {
    uint32_t a;
    asm("{ .reg .u64 t; cvta.to.shared.u64 t, %1; cvt.u32.u64 %0, t; }" : "=r"(a) : "l"(p));
    return a;
}
__device__ __forceinline__ uint32_t f2tf32(float x) {
    uint32_t r; asm("cvt.rna.tf32.f32 %0, %1;" : "=r"(r) : "f"(x)); return r;
}
#define STS32(a, v)  asm volatile("st.shared.b32 [%0], %1;" :: "r"(a), "r"(v) : "memory")
#define LDS64(v0, v1, a) asm volatile("ld.shared.v2.b32 {%0,%1}, [%2];" : "=r"(v0), "=r"(v1) : "r"(a))

__device__ __forceinline__ void mma_tf32(float* d, const uint32_t* a, const uint32_t* b) {
    asm volatile("mma.sync.aligned.m16n8k8.row.col.f32.tf32.tf32.f32 "
        "{%0,%1,%2,%3}, {%4,%5,%6,%7}, {%8,%9}, {%0,%1,%2,%3};"
        : "+f"(d[0]), "+f"(d[1]), "+f"(d[2]), "+f"(d[3])
        : "r"(a[0]), "r"(a[1]), "r"(a[2]), "r"(a[3]), "r"(b[0]), "r"(b[1]));
}

// K-permutation within a 32-float row: p = (k>>3)*8 + (k&3)*2 + ((k>>2)&1)
__device__ __forceinline__ uint32_t permk(uint32_t k) {
    return (k >> 3) * 8u + (k & 3u) * 2u + ((k >> 2) & 1u);
}
// swizzled byte offset within a tile for (row, permuted-pos p)
__device__ __forceinline__ uint32_t swoff(uint32_t row, uint32_t p) {
    return row * 128u + ((((p >> 2) ^ ((row & 3u) << 1)) & 7u) << 4) + ((p & 3u) << 2);
}

__device__ __forceinline__ float gelu_tanh(float v) {
    const float c = 0.7978845608028654f;
    float t = tanhf(c * (v + 0.044715f * v * v * v));
    return 0.5f * v * (1.0f + t);
}

// ---------------- kernel 1: zero counts + output ------------------------------
__global__ void zero_kernel(float* __restrict__ out) {
    int idx = blockIdx.x * blockDim.x + threadIdx.x;
    if (idx < EE) g_counts[idx] = 0;
    size_t total = (size_t)NTOK * HH;
    size_t stride = (size_t)gridDim.x * blockDim.x;
    for (size_t i = idx; i < total; i += stride) out[i] = 0.0f;
}

// ---------------- kernel 2: router --------------------------------------------
__global__ __launch_bounds__(256) void router_kernel(
    const float* __restrict__ x, const float* __restrict__ Wg)
{
    int warp = threadIdx.x >> 5, lane = threadIdx.x & 31;
    int token = blockIdx.x * 8 + warp;
    if (token >= NTOK) return;

    const float* xr = x + (size_t)token * HH;
    float acc[EE];
#pragma unroll
    for (int e = 0; e < EE; e++) acc[e] = 0.0f;
    for (int k = lane; k < HH; k += 32) {
        float xv = xr[k];
        const float* wr = Wg + (size_t)k * EE;
        float4 w0 = *(const float4*)(wr);
        float4 w1 = *(const float4*)(wr + 4);
        acc[0] += xv * w0.x; acc[1] += xv * w0.y;
        acc[2] += xv * w0.z; acc[3] += xv * w0.w;
        acc[4] += xv * w1.x; acc[5] += xv * w1.y;
        acc[6] += xv * w1.z; acc[7] += xv * w1.w;
    }
#pragma unroll
    for (int off = 16; off > 0; off >>= 1)
#pragma unroll
        for (int e = 0; e < EE; e++)
            acc[e] += __shfl_xor_sync(0xFFFFFFFFu, acc[e], off);

    if (lane == 0) {
        int i0 = 0;
#pragma unroll
        for (int e = 1; e < EE; e++) if (acc[e] > acc[i0]) i0 = e;
        int i1 = (i0 == 0) ? 1 : 0;
#pragma unroll
        for (int e = 0; e < EE; e++)
            if (e != i0 && acc[e] > acc[i1]) i1 = e;
        float p1 = expf(acc[i1] - acc[i0]);
        float denom = 1.0f + p1;
        float w0 = 1.0f / denom, w1 = p1 / denom;
        int p = atomicAdd(&g_counts[i0], 1);
        g_tlist[i0 * NTOK + p] = token; g_glist[i0 * NTOK + p] = w0;
        p = atomicAdd(&g_counts[i1], 1);
        g_tlist[i1 * NTOK + p] = token; g_glist[i1 * NTOK + p] = w1;
    }
}

// ---------------- kernel 3: offsets --------------------------------------------
__global__ void offsets_kernel() {
    if (threadIdx.x == 0 && blockIdx.x == 0) {
        int s = 0;
        for (int e = 0; e < EE; e++) { g_offsets[e] = s; s += g_counts[e]; }
    }
}

// ---------------- mma.sync tf32 grouped GEMM -----------------------------------
// Tile 128x128, BK=32. 256 thr = 8 warps, warpM=wid&3 (32 rows), warpN=wid>>2 (64 cols).
// SMEM per buffer: A 128x128B (16KB) + B 128x128B (16KB); double buffered = 64KB.
#define SMEM_DYN_BYTES (64 * 1024 + 256)

// ---- shared mainloop body as a macro (NC differs; epilogue differs) ----
#define GEMM_PROLOG() \
    const int t = threadIdx.x, lane = t & 31, wid = t >> 5; \
    const int warpM = wid & 3, warpN = wid >> 2; \
    const int lg = lane >> 2, lc = lane & 3; \
    extern __shared__ float dyn[]; \
    const uint32_t sbase = (smem_u32(dyn) + 127u) & ~127u; \
    const int arow = t >> 1, ah = t & 1; \
    const int kr = t >> 3, nb = t & 7; \
    const uint32_t pk = permk((uint32_t)kr); \
    const uint32_t bcol = (((pk >> 2) ^ (((uint32_t)nb & 3u) << 1)) << 4) + ((pk & 3u) << 2); \
    uint32_t chunkoff[4]; \
    _Pragma("unroll") \
    for (int ks = 0; ks < 4; ks++) \
        chunkoff[ks] = ((((uint32_t)(ks * 2 + (lc >> 1)) ^ (uint32_t)((lg & 3) << 1)) & 7u) << 4) \
                       + (uint32_t)((lc & 1) << 3); \
    float acc[2][8][4]; \
    _Pragma("unroll") \
    for (int mt = 0; mt < 2; mt++) \
        _Pragma("unroll") \
        for (int nt = 0; nt < 8; nt++) \
            _Pragma("unroll") \
            for (int q = 0; q < 4; q++) acc[mt][nt][q] = 0.0f;

#define LOAD_CHUNK(cc) do { \
    const int k0_ = (cc) * 32; \
    if (aval) { \
        _Pragma("unroll") \
        for (int i = 0; i < 4; i++) av[i] = *(const float4*)(aptr + k0_ + i * 4); \
    } else { \
        _Pragma("unroll") \
        for (int i = 0; i < 4; i++) av[i] = make_float4(0.f, 0.f, 0.f, 0.f); \
    } \
    const float* bp_ = Bsrc + (size_t)(k0_ + kr) * LDB + ntile + nb; \
    _Pragma("unroll") \
    for (int i = 0; i < 16; i++) bv[i] = bp_[8 * i]; \
} while (0)

#define STORE_CHUNK(cc) do { \
    const uint32_t ab_ = sbase + (uint32_t)((cc) & 1) * 32768u; \
    const uint32_t bb_ = ab_ + 16384u; \
    const float* afl_ = (const float*)av; \
    _Pragma("unroll") \
    for (int q = 0; q < 4; q++) \
        _Pragma("unroll") \
        for (int j = 0; j < 4; j++) { \
            uint32_t p_ = (uint32_t)((ah * 2 + (q >> 1)) * 8 + j * 2 + (q & 1)); \
            STS32(ab_ + swoff((uint32_t)arow, p_), f2tf32(afl_[q * 4 + j])); \
        } \
    _Pragma("unroll") \
    for (int i = 0; i < 16; i++) \
        STS32(bb_ + (uint32_t)(nb + 8 * i) * 128u + bcol, f2tf32(bv[i])); \
} while (0)

#define COMPUTE_CHUNK(cc) do { \
    const uint32_t ab_ = sbase + (uint32_t)((cc) & 1) * 32768u; \
    const uint32_t abase_ = ab_ + (uint32_t)(warpM * 32 + lg) * 128u; \
    const uint32_t bbase_ = ab_ + 16384u + (uint32_t)(warpN * 64 + lg) * 128u; \
    _Pragma("unroll") \
    for (int ks = 0; ks < 4; ks++) { \
        const uint32_t aa_ = abase_ + chunkoff[ks]; \
        const uint32_t ba_ = bbase_ + chunkoff[ks]; \
        uint32_t af[2][4]; \
        _Pragma("unroll") \
        for (int mt = 0; mt < 2; mt++) { \
            LDS64(af[mt][0], af[mt][2], aa_ + mt * 2048); \
            LDS64(af[mt][1], af[mt][3], aa_ + mt * 2048 + 1024); \
        } \
        uint32_t bf[8][2]; \
        _Pragma("unroll") \
        for (int nt = 0; nt < 8; nt++) LDS64(bf[nt][0], bf[nt][1], ba_ + nt * 1024); \
        _Pragma("unroll") \
        for (int mt = 0; mt < 2; mt++) \
            _Pragma("unroll") \
            for (int nt = 0; nt < 8; nt++) \
                mma_tf32(acc[mt][nt], af[mt], bf[nt]); \
    } \
} while (0)

// kernel 4: hdd[slot,:] = gelu( x[token,:] @ W1[e] + b1[e] )
__global__ __launch_bounds__(256) void gemm1_mma(
    const float* __restrict__ x, const float* __restrict__ W1,
    const float* __restrict__ b1)
{
    const int e = blockIdx.z;
    const int count = g_counts[e];
    const int mtile = blockIdx.y * 128;
    if (mtile >= count) return;
    const int off = g_offsets[e];
    const int ntile = blockIdx.x * 128;
    const float* Bsrc = W1 + (size_t)e * HH * FF;
    const int LDB = FF;

    GEMM_PROLOG();

    const int m_a = mtile + arow;
    const bool aval = (m_a < count);
    const float* aptr = aval ? (x + (size_t)g_tlist[e * NTOK + m_a] * HH + ah * 16) : x;

    float4 av[4]; float bv[16];
    const int NC = HH / 32;
    LOAD_CHUNK(0);
    STORE_CHUNK(0);
#pragma unroll 1
    for (int c = 0; c < NC; ++c) {
        const int cn = c + 1;
        if (cn < NC) LOAD_CHUNK(cn);
        __syncthreads();
        COMPUTE_CHUNK(c);
        if (cn < NC) STORE_CHUNK(cn);
    }

    // epilogue: bias + gelu -> g_hdd
#pragma unroll
    for (int nt = 0; nt < 8; nt++) {
        const int ncol = warpN * 64 + nt * 8 + lc * 2;
        const float2 bias = *(const float2*)(b1 + (size_t)e * FF + ntile + ncol);
#pragma unroll
        for (int mt = 0; mt < 2; mt++) {
            const int m0 = mtile + warpM * 32 + mt * 16 + lg;
            if (m0 < count) {
                float2 v;
                v.x = gelu_tanh(acc[mt][nt][0] + bias.x);
                v.y = gelu_tanh(acc[mt][nt][1] + bias.y);
                *(float2*)(g_hdd + (size_t)(off + m0) * FF + ntile + ncol) = v;
            }
            const int m1 = m0 + 8;
            if (m1 < count) {
                float2 v;
                v.x = gelu_tanh(acc[mt][nt][2] + bias.x);
                v.y = gelu_tanh(acc[mt][nt][3] + bias.y);
                *(float2*)(g_hdd + (size_t)(off + m1) * FF + ntile + ncol) = v;
            }
        }
    }
}

// kernel 5: out[token,:] += gate * ( hdd[slot,:] @ W2[e] + b2[e] )
__global__ __launch_bounds__(256) void gemm2_mma(
    const float* __restrict__ W2, const float* __restrict__ b2,
    float* __restrict__ out)
{
    const int e = blockIdx.z;
    const int count = g_counts[e];
    const int mtile = blockIdx.y * 128;
    if (mtile >= count) return;
    const int off = g_offsets[e];
    const int ntile = blockIdx.x * 128;
    const float* Bsrc = W2 + (size_t)e * FF * HH;
    const int LDB = HH;

    GEMM_PROLOG();

    const int m_a = mtile + arow;
    const bool aval = (m_a < count);
    const float* aptr = g_hdd + (size_t)(off + (aval ? m_a : 0)) * FF + ah * 16;

    float4 av[4]; float bv[16];
    const int NC = FF / 32;
    LOAD_CHUNK(0);
    STORE_CHUNK(0);
#pragma unroll 1
    for (int c = 0; c < NC; ++c) {
        const int cn = c + 1;
        if (cn < NC) LOAD_CHUNK(cn);
        __syncthreads();
        COMPUTE_CHUNK(c);
        if (cn < NC) STORE_CHUNK(cn);
    }

    // epilogue: gate * (acc + b2) atomically into out
#pragma unroll
    for (int mt = 0; mt < 2; mt++) {
#pragma unroll
        for (int half = 0; half < 2; half++) {
            const int m = mtile + warpM * 32 + mt * 16 + lg + half * 8;
            if (m >= count) continue;
            const int tok = g_tlist[e * NTOK + m];
            const float g = g_glist[e * NTOK + m];
            float* dst = out + (size_t)tok * HH + ntile;
            const float* b2r = b2 + (size_t)e * HH + ntile;
#pragma unroll
            for (int nt = 0; nt < 8; nt++) {
                const int ncol = warpN * 64 + nt * 8 + lc * 2;
                atomicAdd(dst + ncol,     g * (acc[mt][nt][half * 2]     + b2r[ncol]));
                atomicAdd(dst + ncol + 1, g * (acc[mt][nt][half * 2 + 1] + b2r[ncol + 1]));
            }
        }
    }
}

// ---------------- launcher ------------------------------------------------------
extern "C" void kernel_launch(void* const* d_in, const int* in_sizes, int n_in,
                              void* d_out, int out_size)
{
    const float* x  = (const float*)d_in[0];
    const float* Wg = (const float*)d_in[1];
    const float* W1 = (const float*)d_in[2];
    const float* b1 = (const float*)d_in[3];
    const float* W2 = (const float*)d_in[4];
    const float* b2 = (const float*)d_in[5];
    float* out = (float*)d_out;

    cudaFuncSetAttribute(gemm1_mma, cudaFuncAttributeMaxDynamicSharedMemorySize, SMEM_DYN_BYTES);
    cudaFuncSetAttribute(gemm2_mma, cudaFuncAttributeMaxDynamicSharedMemorySize, SMEM_DYN_BYTES);

    zero_kernel<<<512, 256>>>(out);
    router_kernel<<<NTOK / 8, 256>>>(x, Wg);
    offsets_kernel<<<1, 32>>>();
    gemm1_mma<<<dim3(FF / 128, NTOK / 128, EE), 256, SMEM_DYN_BYTES>>>(x, W1, b1);
    gemm2_mma<<<dim3(HH / 128, NTOK / 128, EE), 256, SMEM_DYN_BYTES>>>(W2, b2, out);
}

// round 4
// speedup vs baseline: 2.9661x; 1.6276x over previous
#include <cuda_runtime.h>
#include <cstdint>
#include <math.h>

#define BB 4
#define SS 4096
#define HH 1024
#define FF 4096
#define EE 8
#define NTOK (BB*SS)        // 16384
#define NSLOT (NTOK*2)      // 32768

#define BM 128
#define BN 256
#define BKC 32
#define NSTAGE 3
#define ASZ 16384           // BM rows * 128B
#define BSZ 32768           // BN rows * 128B
#define SMEM_DYN (NSTAGE*(ASZ+BSZ) + 256)

// ---------------- scratch ----------------------------------------------------
__device__ int   g_counts[EE];
__device__ int   g_offsets[EE];
__device__ int   g_tlist[EE*NTOK];
__device__ float g_glist[EE*NTOK];
__device__ float g_hdd[(size_t)NSLOT * FF];

// ---------------- helpers -----------------------------------------------------
__device__ __forceinline__ uint32_t smem_u32(const void* p) {
    uint32_t a;
    asm("{ .reg .u64 t; cvta.to.shared.u64 t, %1; cvt.u32.u64 %0, t; }" : "=r"(a) : "l"(p));
    return a;
}
__device__ __forceinline__ uint32_t f2tf32(float x) {
    uint32_t r; asm("cvt.rna.tf32.f32 %0, %1;" : "=r"(r) : "f"(x)); return r;
}
#define STS32(a, v)  asm volatile("st.shared.b32 [%0], %1;" :: "r"(a), "r"(v) : "memory")
#define STS128(a, v0, v1, v2, v3) \
    asm volatile("st.shared.v4.b32 [%0], {%1,%2,%3,%4};" :: "r"(a), "r"(v0), "r"(v1), "r"(v2), "r"(v3) : "memory")

__device__ __forceinline__ void ldsm4(uint32_t* r, uint32_t a) {
    asm volatile("ldmatrix.sync.aligned.m8n8.x4.shared.b16 {%0,%1,%2,%3}, [%4];"
        : "=r"(r[0]), "=r"(r[1]), "=r"(r[2]), "=r"(r[3]) : "r"(a));
}
__device__ __forceinline__ void mma_tf32(float* d, const uint32_t* a, const uint32_t* b) {
    asm volatile("mma.sync.aligned.m16n8k8.row.col.f32.tf32.tf32.f32 "
        "{%0,%1,%2,%3}, {%4,%5,%6,%7}, {%8,%9}, {%0,%1,%2,%3};"
        : "+f"(d[0]), "+f"(d[1]), "+f"(d[2]), "+f"(d[3])
        : "r"(a[0]), "r"(a[1]), "r"(a[2]), "r"(a[3]), "r"(b[0]), "r"(b[1]));
}
__device__ __forceinline__ float gelu_tanh(float v) {
    const float c = 0.7978845608028654f;
    float t = tanhf(c * (v + 0.044715f * v * v * v));
    return 0.5f * v * (1.0f + t);
}

// ---------------- kernel 1: zero counts + output ------------------------------
__global__ void zero_kernel(float* __restrict__ out) {
    int idx = blockIdx.x * blockDim.x + threadIdx.x;
    if (idx < EE) g_counts[idx] = 0;
    size_t total = (size_t)NTOK * HH;
    size_t stride = (size_t)gridDim.x * blockDim.x;
    for (size_t i = idx; i < total; i += stride) out[i] = 0.0f;
}

// ---------------- kernel 2: router --------------------------------------------
__global__ __launch_bounds__(256) void router_kernel(
    const float* __restrict__ x, const float* __restrict__ Wg)
{
    int warp = threadIdx.x >> 5, lane = threadIdx.x & 31;
    int token = blockIdx.x * 8 + warp;
    if (token >= NTOK) return;

    const float* xr = x + (size_t)token * HH;
    float acc[EE];
#pragma unroll
    for (int e = 0; e < EE; e++) acc[e] = 0.0f;
    for (int k = lane; k < HH; k += 32) {
        float xv = xr[k];
        const float* wr = Wg + (size_t)k * EE;
        float4 w0 = *(const float4*)(wr);
        float4 w1 = *(const float4*)(wr + 4);
        acc[0] += xv * w0.x; acc[1] += xv * w0.y;
        acc[2] += xv * w0.z; acc[3] += xv * w0.w;
        acc[4] += xv * w1.x; acc[5] += xv * w1.y;
        acc[6] += xv * w1.z; acc[7] += xv * w1.w;
    }
#pragma unroll
    for (int off = 16; off > 0; off >>= 1)
#pragma unroll
        for (int e = 0; e < EE; e++)
            acc[e] += __shfl_xor_sync(0xFFFFFFFFu, acc[e], off);

    if (lane == 0) {
        int i0 = 0;
#pragma unroll
        for (int e = 1; e < EE; e++) if (acc[e] > acc[i0]) i0 = e;
        int i1 = (i0 == 0) ? 1 : 0;
#pragma unroll
        for (int e = 0; e < EE; e++)
            if (e != i0 && acc[e] > acc[i1]) i1 = e;
        float p1 = expf(acc[i1] - acc[i0]);
        float denom = 1.0f + p1;
        float w0 = 1.0f / denom, w1 = p1 / denom;
        int p = atomicAdd(&g_counts[i0], 1);
        g_tlist[i0 * NTOK + p] = token; g_glist[i0 * NTOK + p] = w0;
        p = atomicAdd(&g_counts[i1], 1);
        g_tlist[i1 * NTOK + p] = token; g_glist[i1 * NTOK + p] = w1;
    }
}

// ---------------- kernel 3: offsets --------------------------------------------
__global__ void offsets_kernel() {
    if (threadIdx.x == 0 && blockIdx.x == 0) {
        int s = 0;
        for (int e = 0; e < EE; e++) { g_offsets[e] = s; s += g_counts[e]; }
    }
}

// =============== grouped GEMM: 128x256 tile, BK=32, 512 thr, ldmatrix ==========
// A smem: row m (0..127) 128B; elem (m,k): chunk=(k>>2)^(m&7), word k&3.
// B smem (transposed): row n (0..255) 128B; elem (n,k): chunk=(k>>2)^(n&7)^((n>>3)&7).
// Warps: warpM = wid&3 (4 x 32 rows), warpN = wid>>2 (4 x 64 cols). Warp tile 32x64.

#define GEMM_PROLOG3() \
    const int t = threadIdx.x, lane = t & 31, wid = t >> 5; \
    const int warpM = wid & 3, warpN = wid >> 2; \
    extern __shared__ float dyn[]; \
    const uint32_t sbase = (smem_u32(dyn) + 127u) & ~127u; \
    const int frow = t >> 2, fq = t & 3; \
    const int fk = t >> 4, fnb = t & 15; \
    uint32_t afoff[2]; \
    _Pragma("unroll") \
    for (int i = 0; i < 2; i++) \
        afoff[i] = (uint32_t)frow * 128u + (uint32_t)(((2 * fq + i) ^ (frow & 7)) << 4); \
    uint32_t bfoff[4]; \
    _Pragma("unroll") \
    for (int j = 0; j < 4; j++) { \
        uint32_t chj = (uint32_t)(((fk >> 2) ^ ((fnb * 4 + j) & 7) ^ ((fnb >> 1) & 7)) & 7); \
        bfoff[j] = (uint32_t)(fnb * 4 + j) * 128u + (chj << 4) + (uint32_t)(fk & 3) * 4u; \
    } \
    const uint32_t rowA128 = (uint32_t)(warpM * 32 + (lane & 15)) * 128u; \
    uint32_t koffA[4]; \
    _Pragma("unroll") \
    for (int ks = 0; ks < 4; ks++) \
        koffA[ks] = (uint32_t)(((2 * ks + (lane >> 4)) ^ (lane & 7)) << 4); \
    const uint32_t rowB128 = (uint32_t)(warpN * 64 + ((lane >> 4) << 3) + (lane & 7)) * 128u; \
    const uint32_t hB = (uint32_t)((lane >> 3) & 1); \
    uint32_t keyN[4]; \
    _Pragma("unroll") \
    for (int p = 0; p < 4; p++) \
        keyN[p] = (uint32_t)((lane & 7) ^ ((p * 2 + (lane >> 4)) & 7)); \
    float acc[2][8][4]; \
    _Pragma("unroll") \
    for (int mt = 0; mt < 2; mt++) \
        _Pragma("unroll") \
        for (int nt = 0; nt < 8; nt++) \
            _Pragma("unroll") \
            for (int q = 0; q < 4; q++) acc[mt][nt][q] = 0.0f; \
    float4 av[2]; float4 bv[4];

#define FILL_LDG(cc) do { \
    const int k0_ = (cc) * BKC; \
    if (aval) { \
        av[0] = *(const float4*)(aptr + k0_ + fq * 8); \
        av[1] = *(const float4*)(aptr + k0_ + fq * 8 + 4); \
    } else { \
        av[0] = make_float4(0.f,0.f,0.f,0.f); av[1] = make_float4(0.f,0.f,0.f,0.f); \
    } \
    const float* bp_ = Bsrc + (size_t)(k0_ + fk) * LDB + ntile + fnb * 4; \
    _Pragma("unroll") \
    for (int i = 0; i < 4; i++) bv[i] = *(const float4*)(bp_ + 64 * i); \
} while (0)

#define FILL_STS(st) do { \
    const uint32_t A_st = sbase + (uint32_t)(st) * (uint32_t)ASZ; \
    const uint32_t B_st = sbase + (uint32_t)(NSTAGE * ASZ) + (uint32_t)(st) * (uint32_t)BSZ; \
    _Pragma("unroll") \
    for (int i = 0; i < 2; i++) { \
        const float4 v_ = av[i]; \
        STS128(A_st + afoff[i], f2tf32(v_.x), f2tf32(v_.y), f2tf32(v_.z), f2tf32(v_.w)); \
    } \
    const float* bf_ = (const float*)bv; \
    _Pragma("unroll") \
    for (int i = 0; i < 4; i++) \
        _Pragma("unroll") \
        for (int j = 0; j < 4; j++) \
            STS32(B_st + bfoff[j] + (uint32_t)i * 8192u, f2tf32(bf_[i * 4 + j])); \
} while (0)

#define COMPUTE(st) do { \
    const uint32_t A_st = sbase + (uint32_t)(st) * (uint32_t)ASZ; \
    const uint32_t B_st = sbase + (uint32_t)(NSTAGE * ASZ) + (uint32_t)(st) * (uint32_t)BSZ; \
    _Pragma("unroll") \
    for (int ks = 0; ks < 4; ks++) { \
        uint32_t af[2][4]; \
        _Pragma("unroll") \
        for (int mt = 0; mt < 2; mt++) \
            ldsm4(af[mt], A_st + rowA128 + (uint32_t)mt * 2048u + koffA[ks]); \
        uint32_t bf[4][4]; \
        _Pragma("unroll") \
        for (int p = 0; p < 4; p++) \
            ldsm4(bf[p], B_st + rowB128 + (uint32_t)p * 2048u + ((((uint32_t)(2 * ks) + hB) ^ keyN[p]) << 4)); \
        _Pragma("unroll") \
        for (int mt = 0; mt < 2; mt++) \
            _Pragma("unroll") \
            for (int p = 0; p < 4; p++) { \
                mma_tf32(acc[mt][2 * p],     af[mt], &bf[p][0]); \
                mma_tf32(acc[mt][2 * p + 1], af[mt], &bf[p][2]); \
            } \
    } \
} while (0)

#define GEMM_MAINLOOP(NC) do { \
    FILL_LDG(0); FILL_STS(0); \
    int sc_ = 0, sf_ = 1; \
    _Pragma("unroll 1") \
    for (int c = 0; c < (NC); ++c) { \
        if (c + 1 < (NC)) { FILL_LDG(c + 1); FILL_STS(sf_); } \
        __syncthreads(); \
        COMPUTE(sc_); \
        sc_ = (sc_ == 2) ? 0 : sc_ + 1; \
        sf_ = (sf_ == 2) ? 0 : sf_ + 1; \
    } \
} while (0)

// kernel 4: hdd[slot,:] = gelu( x[token,:] @ W1[e] + b1[e] )
__global__ __launch_bounds__(512) void gemm1_mma(
    const float* __restrict__ x, const float* __restrict__ W1,
    const float* __restrict__ b1)
{
    const int e = blockIdx.z;
    const int count = g_counts[e];
    const int mtile = blockIdx.y * BM;
    if (mtile >= count) return;
    const int off = g_offsets[e];
    const int ntile = blockIdx.x * BN;
    const float* Bsrc = W1 + (size_t)e * HH * FF;
    const int LDB = FF;

    GEMM_PROLOG3();

    const int m_a = mtile + frow;
    const bool aval = (m_a < count);
    const float* aptr = aval ? (x + (size_t)g_tlist[e * NTOK + m_a] * HH) : x;

    GEMM_MAINLOOP(HH / BKC);

    const int lg = lane >> 2, lc = lane & 3;
#pragma unroll
    for (int nt = 0; nt < 8; nt++) {
        const int ncol = ntile + warpN * 64 + nt * 8 + lc * 2;
        const float2 bias = *(const float2*)(b1 + (size_t)e * FF + ncol);
#pragma unroll
        for (int mt = 0; mt < 2; mt++) {
            const int m0 = mtile + warpM * 32 + mt * 16 + lg;
            if (m0 < count) {
                float2 v;
                v.x = gelu_tanh(acc[mt][nt][0] + bias.x);
                v.y = gelu_tanh(acc[mt][nt][1] + bias.y);
                *(float2*)(g_hdd + (size_t)(off + m0) * FF + ncol) = v;
            }
            const int m1 = m0 + 8;
            if (m1 < count) {
                float2 v;
                v.x = gelu_tanh(acc[mt][nt][2] + bias.x);
                v.y = gelu_tanh(acc[mt][nt][3] + bias.y);
                *(float2*)(g_hdd + (size_t)(off + m1) * FF + ncol) = v;
            }
        }
    }
}

// kernel 5: out[token,:] += gate * ( hdd[slot,:] @ W2[e] + b2[e] )
__global__ __launch_bounds__(512) void gemm2_mma(
    const float* __restrict__ W2, const float* __restrict__ b2,
    float* __restrict__ out)
{
    const int e = blockIdx.z;
    const int count = g_counts[e];
    const int mtile = blockIdx.y * BM;
    if (mtile >= count) return;
    const int off = g_offsets[e];
    const int ntile = blockIdx.x * BN;
    const float* Bsrc = W2 + (size_t)e * FF * HH;
    const int LDB = HH;

    GEMM_PROLOG3();

    const int m_a = mtile + frow;
    const bool aval = (m_a < count);
    const float* aptr = g_hdd + (size_t)(off + (aval ? m_a : 0)) * FF;

    GEMM_MAINLOOP(FF / BKC);

    const int lg = lane >> 2, lc = lane & 3;
#pragma unroll
    for (int mt = 0; mt < 2; mt++) {
#pragma unroll
        for (int half = 0; half < 2; half++) {
            const int m = mtile + warpM * 32 + mt * 16 + lg + half * 8;
            if (m >= count) continue;
            const int tok = g_tlist[e * NTOK + m];
            const float g = g_glist[e * NTOK + m];
            float* dst = out + (size_t)tok * HH + ntile;
            const float* b2r = b2 + (size_t)e * HH + ntile;
#pragma unroll
            for (int nt = 0; nt < 8; nt++) {
                const int ncol = warpN * 64 + nt * 8 + lc * 2;
                atomicAdd(dst + ncol,     g * (acc[mt][nt][half * 2]     + b2r[ncol]));
                atomicAdd(dst + ncol + 1, g * (acc[mt][nt][half * 2 + 1] + b2r[ncol + 1]));
            }
        }
    }
}

// ---------------- launcher ------------------------------------------------------
extern "C" void kernel_launch(void* const* d_in, const int* in_sizes, int n_in,
                              void* d_out, int out_size)
{
    const float* x  = (const float*)d_in[0];
    const float* Wg = (const float*)d_in[1];
    const float* W1 = (const float*)d_in[2];
    const float* b1 = (const float*)d_in[3];
    const float* W2 = (const float*)d_in[4];
    const float* b2 = (const float*)d_in[5];
    float* out = (float*)d_out;

    cudaFuncSetAttribute(gemm1_mma, cudaFuncAttributeMaxDynamicSharedMemorySize, SMEM_DYN);
    cudaFuncSetAttribute(gemm2_mma, cudaFuncAttributeMaxDynamicSharedMemorySize, SMEM_DYN);

    zero_kernel<<<512, 256>>>(out);
    router_kernel<<<NTOK / 8, 256>>>(x, Wg);
    offsets_kernel<<<1, 32>>>();
    gemm1_mma<<<dim3(FF / BN, NTOK / BM, EE), 512, SMEM_DYN>>>(x, W1, b1);
    gemm2_mma<<<dim3(HH / BN, NTOK / BM, EE), 512, SMEM_DYN>>>(W2, b2, out);
}

// round 6
// speedup vs baseline: 3.2048x; 1.0805x over previous
#include <cuda_runtime.h>
#include <cstdint>
#include <math.h>

#define BB 4
#define SS 4096
#define HH 1024
#define FF 4096
#define EE 8
#define NTOK (BB*SS)        // 16384
#define NSLOT (NTOK*2)      // 32768

#define BM 128
#define BN 256
#define BKC 32
#define NSTAGE 3
#define ASZ 16384           // BM rows * 128B
#define BSZ 32768           // BN rows * 128B
#define SMEM_DYN (NSTAGE*(ASZ+BSZ) + 256)

#define W1_NT (FF/BN)       // 16
#define W1_NC (HH/BKC)      // 32
#define W2_NT (HH/BN)       // 4
#define W2_NC (FF/BKC)      // 128

// ---------------- scratch ----------------------------------------------------
__device__ int   g_counts[EE];
__device__ int   g_offsets[EE];
__device__ int   g_tlist[EE*NTOK];
__device__ float g_glist[EE*NTOK];
__device__ float g_hdd[(size_t)NSLOT * FF];              // tf32-bits hidden acts
__device__ float g_xt[(size_t)NTOK * HH];                // tf32-bits x
__device__ float g_w1t[(size_t)EE * HH * FF];            // smem-image W1
__device__ float g_w2t[(size_t)EE * FF * HH];            // smem-image W2

// ---------------- helpers -----------------------------------------------------
__device__ __forceinline__ uint32_t smem_u32(const void* p) {
    uint32_t a;
    asm("{ .reg .u64 t; cvta.to.shared.u64 t, %1; cvt.u32.u64 %0, t; }" : "=r"(a) : "l"(p));
    return a;
}
__device__ __forceinline__ uint32_t f2tf32(float x) {
    uint32_t r; asm("cvt.rna.tf32.f32 %0, %1;" : "=r"(r) : "f"(x)); return r;
}
#define STS128(a, v) \
    asm volatile("st.shared.v4.b32 [%0], {%1,%2,%3,%4};" :: "r"(a), \
        "r"(__float_as_uint((v).x)), "r"(__float_as_uint((v).y)), \
        "r"(__float_as_uint((v).z)), "r"(__float_as_uint((v).w)) : "memory")

__device__ __forceinline__ void ldsm4(uint32_t* r, uint32_t a) {
    asm volatile("ldmatrix.sync.aligned.m8n8.x4.shared.b16 {%0,%1,%2,%3}, [%4];"
        : "=r"(r[0]), "=r"(r[1]), "=r"(r[2]), "=r"(r[3]) : "r"(a));
}
__device__ __forceinline__ void mma_tf32(float* d, const uint32_t* a, const uint32_t* b) {
    asm volatile("mma.sync.aligned.m16n8k8.row.col.f32.tf32.tf32.f32 "
        "{%0,%1,%2,%3}, {%4,%5,%6,%7}, {%8,%9}, {%0,%1,%2,%3};"
        : "+f"(d[0]), "+f"(d[1]), "+f"(d[2]), "+f"(d[3])
        : "r"(a[0]), "r"(a[1]), "r"(a[2]), "r"(a[3]), "r"(b[0]), "r"(b[1]));
}
__device__ __forceinline__ float gelu_tanh(float v) {
    const float c = 0.7978845608028654f;
    float t = tanhf(c * (v + 0.044715f * v * v * v));
    return 0.5f * v * (1.0f + t);
}

// ---------------- kernel 1: zero counts/out + convert x to tf32 ---------------
__global__ void prep_zero_x(const float* __restrict__ x, float* __restrict__ out) {
    int idx = blockIdx.x * blockDim.x + threadIdx.x;
    if (idx < EE) g_counts[idx] = 0;
    size_t total4 = (size_t)NTOK * HH / 4;
    size_t stride = (size_t)gridDim.x * blockDim.x;
    const float4* x4 = (const float4*)x;
    float4* o4 = (float4*)out;
    float4* xt4 = (float4*)g_xt;
    for (size_t i = idx; i < total4; i += stride) {
        o4[i] = make_float4(0.f, 0.f, 0.f, 0.f);
        float4 v = x4[i];
        float4 w;
        w.x = __uint_as_float(f2tf32(v.x));
        w.y = __uint_as_float(f2tf32(v.y));
        w.z = __uint_as_float(f2tf32(v.z));
        w.w = __uint_as_float(f2tf32(v.w));
        xt4[i] = w;
    }
}

// ---------------- kernel 1b: weight prep (transpose+cvt into smem image) -------
// dst block (e, tn, c) at bid*8192 floats; elem (n,k): n*32 + ch*4 + (k&3),
// ch = ((k>>2) ^ (n&7) ^ ((n>>3)&7)) & 7   (matches GEMM smem B layout)
__global__ __launch_bounds__(256) void prep_w(
    const float* __restrict__ W, float* __restrict__ dst, int Kdim, int Ndim)
{
    const int NCk = Kdim >> 5;
    const int NT = Ndim >> 8;
    const int bid = blockIdx.x;
    const int c = bid % NCk;
    const int tmp = bid / NCk;
    const int tn = tmp % NT;
    const int e = tmp / NT;
    const int n = threadIdx.x;

    const float* src = W + (size_t)e * Kdim * Ndim + (size_t)(c * 32) * Ndim + tn * 256 + n;
    float* out = dst + (size_t)bid * 8192 + (uint32_t)n * 32u;

    uint32_t w[32];
#pragma unroll
    for (int kk = 0; kk < 32; kk++) w[kk] = f2tf32(src[(size_t)kk * Ndim]);
#pragma unroll
    for (int ch4 = 0; ch4 < 8; ch4++) {
        uint32_t ch = (uint32_t)((ch4 ^ (n & 7) ^ ((n >> 3) & 7)) & 7);
        float4 v = make_float4(__uint_as_float(w[ch4 * 4]), __uint_as_float(w[ch4 * 4 + 1]),
                               __uint_as_float(w[ch4 * 4 + 2]), __uint_as_float(w[ch4 * 4 + 3]));
        *(float4*)(out + ch * 4) = v;
    }
}

// ---------------- kernel 2: router --------------------------------------------
__global__ __launch_bounds__(256) void router_kernel(
    const float* __restrict__ x, const float* __restrict__ Wg)
{
    int warp = threadIdx.x >> 5, lane = threadIdx.x & 31;
    int token = blockIdx.x * 8 + warp;
    if (token >= NTOK) return;

    const float* xr = x + (size_t)token * HH;
    float acc[EE];
#pragma unroll
    for (int e = 0; e < EE; e++) acc[e] = 0.0f;
    for (int k = lane; k < HH; k += 32) {
        float xv = xr[k];
        const float* wr = Wg + (size_t)k * EE;
        float4 w0 = *(const float4*)(wr);
        float4 w1 = *(const float4*)(wr + 4);
        acc[0] += xv * w0.x; acc[1] += xv * w0.y;
        acc[2] += xv * w0.z; acc[3] += xv * w0.w;
        acc[4] += xv * w1.x; acc[5] += xv * w1.y;
        acc[6] += xv * w1.z; acc[7] += xv * w1.w;
    }
#pragma unroll
    for (int off = 16; off > 0; off >>= 1)
#pragma unroll
        for (int e = 0; e < EE; e++)
            acc[e] += __shfl_xor_sync(0xFFFFFFFFu, acc[e], off);

    if (lane == 0) {
        int i0 = 0;
#pragma unroll
        for (int e = 1; e < EE; e++) if (acc[e] > acc[i0]) i0 = e;
        int i1 = (i0 == 0) ? 1 : 0;
#pragma unroll
        for (int e = 0; e < EE; e++)
            if (e != i0 && acc[e] > acc[i1]) i1 = e;
        float p1 = expf(acc[i1] - acc[i0]);
        float denom = 1.0f + p1;
        float w0 = 1.0f / denom, w1 = p1 / denom;
        int p = atomicAdd(&g_counts[i0], 1);
        g_tlist[i0 * NTOK + p] = token; g_glist[i0 * NTOK + p] = w0;
        p = atomicAdd(&g_counts[i1], 1);
        g_tlist[i1 * NTOK + p] = token; g_glist[i1 * NTOK + p] = w1;
    }
}

// ---------------- kernel 3: offsets --------------------------------------------
__global__ void offsets_kernel() {
    if (threadIdx.x == 0 && blockIdx.x == 0) {
        int s = 0;
        for (int e = 0; e < EE; e++) { g_offsets[e] = s; s += g_counts[e]; }
    }
}

// =============== grouped GEMM: 128x256 tile, BK=32, 512 thr ====================
// A operand (tokens/hdd): already tf32 bits; B operand: preprocessed smem image.

#define GEMM_PROLOG3() \
    const int t = threadIdx.x, lane = t & 31, wid = t >> 5; \
    const int warpM = wid & 3, warpN = wid >> 2; \
    extern __shared__ float dyn[]; \
    const uint32_t sbase = (smem_u32(dyn) + 127u) & ~127u; \
    const int frow = t >> 2, fq = t & 3; \
    uint32_t afoff[2]; \
    _Pragma("unroll") \
    for (int i = 0; i < 2; i++) \
        afoff[i] = (uint32_t)frow * 128u + (uint32_t)(((2 * fq + i) ^ (frow & 7)) << 4); \
    const uint32_t rowA128 = (uint32_t)(warpM * 32 + (lane & 15)) * 128u; \
    uint32_t koffA[4]; \
    _Pragma("unroll") \
    for (int ks = 0; ks < 4; ks++) \
        koffA[ks] = (uint32_t)(((2 * ks + (lane >> 4)) ^ (lane & 7)) << 4); \
    const uint32_t rowB128 = (uint32_t)(warpN * 64 + ((lane >> 4) << 3) + (lane & 7)) * 128u; \
    const uint32_t hB = (uint32_t)((lane >> 3) & 1); \
    uint32_t keyN[4]; \
    _Pragma("unroll") \
    for (int p = 0; p < 4; p++) \
        keyN[p] = (uint32_t)((lane & 7) ^ ((p * 2 + (lane >> 4)) & 7)); \
    float acc[2][8][4]; \
    _Pragma("unroll") \
    for (int mt = 0; mt < 2; mt++) \
        _Pragma("unroll") \
        for (int nt = 0; nt < 8; nt++) \
            _Pragma("unroll") \
            for (int q = 0; q < 4; q++) acc[mt][nt][q] = 0.0f; \
    float4 av[2]; float4 bq[4];

#define FILL_LDG(cc) do { \
    const int k0_ = (cc) * BKC; \
    if (aval) { \
        av[0] = *(const float4*)(aptr + k0_ + fq * 8); \
        av[1] = *(const float4*)(aptr + k0_ + fq * 8 + 4); \
    } else { \
        av[0] = make_float4(0.f,0.f,0.f,0.f); av[1] = make_float4(0.f,0.f,0.f,0.f); \
    } \
    const float4* bp_ = (const float4*)(bscr + (size_t)(cc) * 8192) + t; \
    _Pragma("unroll") \
    for (int i = 0; i < 4; i++) bq[i] = bp_[i * 512]; \
} while (0)

#define FILL_STS(st) do { \
    const uint32_t A_st = sbase + (uint32_t)(st) * (uint32_t)ASZ; \
    const uint32_t B_st = sbase + (uint32_t)(NSTAGE * ASZ) + (uint32_t)(st) * (uint32_t)BSZ; \
    STS128(A_st + afoff[0], av[0]); \
    STS128(A_st + afoff[1], av[1]); \
    const uint32_t bo_ = B_st + (uint32_t)t * 16u; \
    _Pragma("unroll") \
    for (int i = 0; i < 4; i++) STS128(bo_ + (uint32_t)i * 8192u, bq[i]); \
} while (0)

#define COMPUTE(st) do { \
    const uint32_t A_st = sbase + (uint32_t)(st) * (uint32_t)ASZ; \
    const uint32_t B_st = sbase + (uint32_t)(NSTAGE * ASZ) + (uint32_t)(st) * (uint32_t)BSZ; \
    _Pragma("unroll") \
    for (int ks = 0; ks < 4; ks++) { \
        uint32_t af[2][4]; \
        _Pragma("unroll") \
        for (int mt = 0; mt < 2; mt++) \
            ldsm4(af[mt], A_st + rowA128 + (uint32_t)mt * 2048u + koffA[ks]); \
        uint32_t bf[4][4]; \
        _Pragma("unroll") \
        for (int p = 0; p < 4; p++) \
            ldsm4(bf[p], B_st + rowB128 + (uint32_t)p * 2048u + ((((uint32_t)(2 * ks) + hB) ^ keyN[p]) << 4)); \
        _Pragma("unroll") \
        for (int mt = 0; mt < 2; mt++) \
            _Pragma("unroll") \
            for (int p = 0; p < 4; p++) { \
                mma_tf32(acc[mt][2 * p],     af[mt], &bf[p][0]); \
                mma_tf32(acc[mt][2 * p + 1], af[mt], &bf[p][2]); \
            } \
    } \
} while (0)

#define GEMM_MAINLOOP(NC) do { \
    FILL_LDG(0); FILL_STS(0); \
    int sc_ = 0, sf_ = 1; \
    _Pragma("unroll 1") \
    for (int c = 0; c < (NC); ++c) { \
        if (c + 1 < (NC)) { FILL_LDG(c + 1); FILL_STS(sf_); } \
        __syncthreads(); \
        COMPUTE(sc_); \
        sc_ = (sc_ == 2) ? 0 : sc_ + 1; \
        sf_ = (sf_ == 2) ? 0 : sf_ + 1; \
    } \
} while (0)

// kernel 4: hdd[slot,:] = tf32( gelu( x[token,:] @ W1[e] + b1[e] ) )
__global__ __launch_bounds__(512) void gemm1_mma(
    const float* __restrict__ b1)
{
    const int e = blockIdx.z;
    const int count = g_counts[e];
    const int mtile = blockIdx.y * BM;
    if (mtile >= count) return;
    const int off = g_offsets[e];
    const int ntile = blockIdx.x * BN;

    GEMM_PROLOG3();

    const float* bscr = g_w1t + (size_t)(e * W1_NT + blockIdx.x) * W1_NC * 8192;
    const int m_a = mtile + frow;
    const bool aval = (m_a < count);
    const float* aptr = aval ? (g_xt + (size_t)g_tlist[e * NTOK + m_a] * HH) : g_xt;

    GEMM_MAINLOOP(W1_NC);

    const int lg = lane >> 2, lc = lane & 3;
#pragma unroll
    for (int nt = 0; nt < 8; nt++) {
        const int ncol = ntile + warpN * 64 + nt * 8 + lc * 2;
        const float2 bias = *(const float2*)(b1 + (size_t)e * FF + ncol);
#pragma unroll
        for (int mt = 0; mt < 2; mt++) {
            const int m0 = mtile + warpM * 32 + mt * 16 + lg;
            if (m0 < count) {
                float2 v;
                v.x = __uint_as_float(f2tf32(gelu_tanh(acc[mt][nt][0] + bias.x)));
                v.y = __uint_as_float(f2tf32(gelu_tanh(acc[mt][nt][1] + bias.y)));
                *(float2*)(g_hdd + (size_t)(off + m0) * FF + ncol) = v;
            }
            const int m1 = m0 + 8;
            if (m1 < count) {
                float2 v;
                v.x = __uint_as_float(f2tf32(gelu_tanh(acc[mt][nt][2] + bias.x)));
                v.y = __uint_as_float(f2tf32(gelu_tanh(acc[mt][nt][3] + bias.y)));
                *(float2*)(g_hdd + (size_t)(off + m1) * FF + ncol) = v;
            }
        }
    }
}

// kernel 5: out[token,:] += gate * ( hdd[slot,:] @ W2[e] + b2[e] )
__global__ __launch_bounds__(512) void gemm2_mma(
    const float* __restrict__ b2, float* __restrict__ out)
{
    const int e = blockIdx.z;
    const int count = g_counts[e];
    const int mtile = blockIdx.y * BM;
    if (mtile >= count) return;
    const int off = g_offsets[e];
    const int ntile = blockIdx.x * BN;

    GEMM_PROLOG3();

    const float* bscr = g_w2t + (size_t)(e * W2_NT + blockIdx.x) * W2_NC * 8192;
    const int m_a = mtile + frow;
    const bool aval = (m_a < count);
    const float* aptr = g_hdd + (size_t)(off + (aval ? m_a : 0)) * FF;

    GEMM_MAINLOOP(W2_NC);

    const int lg = lane >> 2, lc = lane & 3;
#pragma unroll
    for (int mt = 0; mt < 2; mt++) {
#pragma unroll
        for (int half = 0; half < 2; half++) {
            const int m = mtile + warpM * 32 + mt * 16 + lg + half * 8;
            if (m >= count) continue;
            const int tok = g_tlist[e * NTOK + m];
            const float g = g_glist[e * NTOK + m];
            float* dst = out + (size_t)tok * HH + ntile;
            const float* b2r = b2 + (size_t)e * HH + ntile;
#pragma unroll
            for (int nt = 0; nt < 8; nt++) {
                const int ncol = warpN * 64 + nt * 8 + lc * 2;
                atomicAdd(dst + ncol,     g * (acc[mt][nt][half * 2]     + b2r[ncol]));
                atomicAdd(dst + ncol + 1, g * (acc[mt][nt][half * 2 + 1] + b2r[ncol + 1]));
            }
        }
    }
}

// ---------------- launcher ------------------------------------------------------
extern "C" void kernel_launch(void* const* d_in, const int* in_sizes, int n_in,
                              void* d_out, int out_size)
{
    const float* x  = (const float*)d_in[0];
    const float* Wg = (const float*)d_in[1];
    const float* W1 = (const float*)d_in[2];
    const float* b1 = (const float*)d_in[3];
    const float* W2 = (const float*)d_in[4];
    const float* b2 = (const float*)d_in[5];
    float* out = (float*)d_out;

    cudaFuncSetAttribute(gemm1_mma, cudaFuncAttributeMaxDynamicSharedMemorySize, SMEM_DYN);
    cudaFuncSetAttribute(gemm2_mma, cudaFuncAttributeMaxDynamicSharedMemorySize, SMEM_DYN);

    float* w1t; cudaGetSymbolAddress((void**)&w1t, g_w1t);
    float* w2t; cudaGetSymbolAddress((void**)&w2t, g_w2t);

    prep_zero_x<<<1024, 256>>>(x, out);
    prep_w<<<EE * W1_NT * W1_NC, 256>>>(W1, w1t, HH, FF);
    prep_w<<<EE * W2_NT * W2_NC, 256>>>(W2, w2t, FF, HH);
    router_kernel<<<NTOK / 8, 256>>>(x, Wg);
    offsets_kernel<<<1, 32>>>();
    gemm1_mma<<<dim3(FF / BN, NTOK / BM, EE), 512, SMEM_DYN>>>(b1);
    gemm2_mma<<<dim3(HH / BN, NTOK / BM, EE), 512, SMEM_DYN>>>(b2, out);
}

// round 7
// speedup vs baseline: 4.0519x; 1.2643x over previous
#include <cuda_runtime.h>
#include <cstdint>
#include <math.h>

#define BB 4
#define SS 4096
#define HH 1024
#define FF 4096
#define EE 8
#define NTOK (BB*SS)        // 16384
#define NSLOT (NTOK*2)      // 32768

#define BM 128
#define BN 256
#define BKC 32
#define NSTAGE 4
#define ASZ 16384           // BM rows * 128B
#define BSZ 32768           // BN rows * 128B
#define STGSZ (ASZ+BSZ)
#define SMEM_DYN (NSTAGE*STGSZ + 256)

#define W1_NT (FF/BN)       // 16
#define W1_NC (HH/BKC)      // 32
#define W2_NT (HH/BN)       // 4
#define W2_NC (FF/BKC)      // 128

// ---------------- scratch ----------------------------------------------------
__device__ int   g_counts[EE];
__device__ int   g_offsets[EE];
__device__ int   g_tlist[EE*NTOK];
__device__ float g_glist[EE*NTOK];
__device__ float g_hdd[(size_t)NSLOT * FF];              // tf32-bits hidden acts
__device__ float g_xt[(size_t)NTOK * HH];                // tf32-bits x
__device__ float g_w1t[(size_t)EE * HH * FF];            // smem-image W1
__device__ float g_w2t[(size_t)EE * FF * HH];            // smem-image W2

// ---------------- helpers -----------------------------------------------------
__device__ __forceinline__ uint32_t smem_u32(const void* p) {
    uint32_t a;
    asm("{ .reg .u64 t; cvta.to.shared.u64 t, %1; cvt.u32.u64 %0, t; }" : "=r"(a) : "l"(p));
    return a;
}
__device__ __forceinline__ uint32_t f2tf32(float x) {
    uint32_t r; asm("cvt.rna.tf32.f32 %0, %1;" : "=r"(r) : "f"(x)); return r;
}
#define CPA16(dst, src, sz) \
    asm volatile("cp.async.cg.shared.global [%0], [%1], 16, %2;" \
        :: "r"(dst), "l"(src), "r"(sz) : "memory")
#define CPA_COMMIT() asm volatile("cp.async.commit_group;" ::: "memory")
#define CPA_WAIT2()  asm volatile("cp.async.wait_group 2;" ::: "memory")

__device__ __forceinline__ void ldsm4(uint32_t* r, uint32_t a) {
    asm volatile("ldmatrix.sync.aligned.m8n8.x4.shared.b16 {%0,%1,%2,%3}, [%4];"
        : "=r"(r[0]), "=r"(r[1]), "=r"(r[2]), "=r"(r[3]) : "r"(a));
}
__device__ __forceinline__ void mma_tf32(float* d, const uint32_t* a, const uint32_t* b) {
    asm volatile("mma.sync.aligned.m16n8k8.row.col.f32.tf32.tf32.f32 "
        "{%0,%1,%2,%3}, {%4,%5,%6,%7}, {%8,%9}, {%0,%1,%2,%3};"
        : "+f"(d[0]), "+f"(d[1]), "+f"(d[2]), "+f"(d[3])
        : "r"(a[0]), "r"(a[1]), "r"(a[2]), "r"(a[3]), "r"(b[0]), "r"(b[1]));
}
__device__ __forceinline__ float gelu_tanh(float v) {
    const float c = 0.7978845608028654f;
    float t = tanhf(c * (v + 0.044715f * v * v * v));
    return 0.5f * v * (1.0f + t);
}

// ---------------- kernel 1: zero counts/out + convert x to tf32 ---------------
__global__ void prep_zero_x(const float* __restrict__ x, float* __restrict__ out) {
    int idx = blockIdx.x * blockDim.x + threadIdx.x;
    if (idx < EE) g_counts[idx] = 0;
    size_t total4 = (size_t)NTOK * HH / 4;
    size_t stride = (size_t)gridDim.x * blockDim.x;
    const float4* x4 = (const float4*)x;
    float4* o4 = (float4*)out;
    float4* xt4 = (float4*)g_xt;
    for (size_t i = idx; i < total4; i += stride) {
        o4[i] = make_float4(0.f, 0.f, 0.f, 0.f);
        float4 v = x4[i];
        float4 w;
        w.x = __uint_as_float(f2tf32(v.x));
        w.y = __uint_as_float(f2tf32(v.y));
        w.z = __uint_as_float(f2tf32(v.z));
        w.w = __uint_as_float(f2tf32(v.w));
        xt4[i] = w;
    }
}

// ---------------- kernel 1b: weight prep (transpose+cvt into smem image) -------
__global__ __launch_bounds__(256) void prep_w(
    const float* __restrict__ W, float* __restrict__ dst, int Kdim, int Ndim)
{
    const int NCk = Kdim >> 5;
    const int NT = Ndim >> 8;
    const int bid = blockIdx.x;
    const int c = bid % NCk;
    const int tmp = bid / NCk;
    const int tn = tmp % NT;
    const int e = tmp / NT;
    const int n = threadIdx.x;

    const float* src = W + (size_t)e * Kdim * Ndim + (size_t)(c * 32) * Ndim + tn * 256 + n;
    float* out = dst + (size_t)bid * 8192 + (uint32_t)n * 32u;

    uint32_t w[32];
#pragma unroll
    for (int kk = 0; kk < 32; kk++) w[kk] = f2tf32(src[(size_t)kk * Ndim]);
#pragma unroll
    for (int ch4 = 0; ch4 < 8; ch4++) {
        uint32_t ch = (uint32_t)((ch4 ^ (n & 7) ^ ((n >> 3) & 7)) & 7);
        float4 v = make_float4(__uint_as_float(w[ch4 * 4]), __uint_as_float(w[ch4 * 4 + 1]),
                               __uint_as_float(w[ch4 * 4 + 2]), __uint_as_float(w[ch4 * 4 + 3]));
        *(float4*)(out + ch * 4) = v;
    }
}

// ---------------- kernel 2: router --------------------------------------------
__global__ __launch_bounds__(256) void router_kernel(
    const float* __restrict__ x, const float* __restrict__ Wg)
{
    int warp = threadIdx.x >> 5, lane = threadIdx.x & 31;
    int token = blockIdx.x * 8 + warp;
    if (token >= NTOK) return;

    const float* xr = x + (size_t)token * HH;
    float acc[EE];
#pragma unroll
    for (int e = 0; e < EE; e++) acc[e] = 0.0f;
    for (int k = lane; k < HH; k += 32) {
        float xv = xr[k];
        const float* wr = Wg + (size_t)k * EE;
        float4 w0 = *(const float4*)(wr);
        float4 w1 = *(const float4*)(wr + 4);
        acc[0] += xv * w0.x; acc[1] += xv * w0.y;
        acc[2] += xv * w0.z; acc[3] += xv * w0.w;
        acc[4] += xv * w1.x; acc[5] += xv * w1.y;
        acc[6] += xv * w1.z; acc[7] += xv * w1.w;
    }
#pragma unroll
    for (int off = 16; off > 0; off >>= 1)
#pragma unroll
        for (int e = 0; e < EE; e++)
            acc[e] += __shfl_xor_sync(0xFFFFFFFFu, acc[e], off);

    if (lane == 0) {
        int i0 = 0;
#pragma unroll
        for (int e = 1; e < EE; e++) if (acc[e] > acc[i0]) i0 = e;
        int i1 = (i0 == 0) ? 1 : 0;
#pragma unroll
        for (int e = 0; e < EE; e++)
            if (e != i0 && acc[e] > acc[i1]) i1 = e;
        float p1 = expf(acc[i1] - acc[i0]);
        float denom = 1.0f + p1;
        float w0 = 1.0f / denom, w1 = p1 / denom;
        int p = atomicAdd(&g_counts[i0], 1);
        g_tlist[i0 * NTOK + p] = token; g_glist[i0 * NTOK + p] = w0;
        p = atomicAdd(&g_counts[i1], 1);
        g_tlist[i1 * NTOK + p] = token; g_glist[i1 * NTOK + p] = w1;
    }
}

// ---------------- kernel 3: offsets --------------------------------------------
__global__ void offsets_kernel() {
    if (threadIdx.x == 0 && blockIdx.x == 0) {
        int s = 0;
        for (int e = 0; e < EE; e++) { g_offsets[e] = s; s += g_counts[e]; }
    }
}

// =============== grouped GEMM: 128x256 tile, BK=32, 512 thr, cp.async ==========
// A operand: tf32-bit rows gathered per token; B operand: preprocessed smem image.
// 4-stage cp.async pipeline, one commit group per chunk, wait_group 2.

#define GEMM_PROLOG3() \
    const int t = threadIdx.x, lane = t & 31, wid = t >> 5; \
    const int warpM = wid & 3, warpN = wid >> 2; \
    extern __shared__ float dyn[]; \
    const uint32_t sbase = (smem_u32(dyn) + 127u) & ~127u; \
    const int frow = t >> 2, fq = t & 3; \
    uint32_t afoff[2]; \
    _Pragma("unroll") \
    for (int i = 0; i < 2; i++) \
        afoff[i] = (uint32_t)frow * 128u + (uint32_t)(((2 * fq + i) ^ (frow & 7)) << 4); \
    const uint32_t rowA128 = (uint32_t)(warpM * 32 + (lane & 15)) * 128u; \
    uint32_t koffA[4]; \
    _Pragma("unroll") \
    for (int ks = 0; ks < 4; ks++) \
        koffA[ks] = (uint32_t)(((2 * ks + (lane >> 4)) ^ (lane & 7)) << 4); \
    const uint32_t rowB128 = (uint32_t)(warpN * 64 + ((lane >> 4) << 3) + (lane & 7)) * 128u; \
    const uint32_t hB = (uint32_t)((lane >> 3) & 1); \
    uint32_t keyN[4]; \
    _Pragma("unroll") \
    for (int p = 0; p < 4; p++) \
        keyN[p] = (uint32_t)((lane & 7) ^ ((p * 2 + (lane >> 4)) & 7)); \
    float acc[2][8][4]; \
    _Pragma("unroll") \
    for (int mt = 0; mt < 2; mt++) \
        _Pragma("unroll") \
        for (int nt = 0; nt < 8; nt++) \
            _Pragma("unroll") \
            for (int q = 0; q < 4; q++) acc[mt][nt][q] = 0.0f;

#define FILL_ASYNC(cc, st) do { \
    const uint32_t A_st = sbase + (uint32_t)(st) * (uint32_t)STGSZ; \
    const uint32_t B_st = A_st + (uint32_t)ASZ; \
    const float* as_ = aptr + (cc) * BKC + fq * 8; \
    CPA16(A_st + afoff[0], as_,     aszf); \
    CPA16(A_st + afoff[1], as_ + 4, aszf); \
    const float4* bp_ = (const float4*)(bscr + (size_t)(cc) * 8192) + t; \
    const uint32_t bo_ = B_st + (uint32_t)t * 16u; \
    _Pragma("unroll") \
    for (int i = 0; i < 4; i++) CPA16(bo_ + (uint32_t)i * 8192u, bp_ + i * 512, 16u); \
} while (0)

#define COMPUTE(st) do { \
    const uint32_t A_st = sbase + (uint32_t)(st) * (uint32_t)STGSZ; \
    const uint32_t B_st = A_st + (uint32_t)ASZ; \
    _Pragma("unroll") \
    for (int ks = 0; ks < 4; ks++) { \
        uint32_t af[2][4]; \
        _Pragma("unroll") \
        for (int mt = 0; mt < 2; mt++) \
            ldsm4(af[mt], A_st + rowA128 + (uint32_t)mt * 2048u + koffA[ks]); \
        uint32_t bf[4][4]; \
        _Pragma("unroll") \
        for (int p = 0; p < 4; p++) \
            ldsm4(bf[p], B_st + rowB128 + (uint32_t)p * 2048u + ((((uint32_t)(2 * ks) + hB) ^ keyN[p]) << 4)); \
        _Pragma("unroll") \
        for (int mt = 0; mt < 2; mt++) \
            _Pragma("unroll") \
            for (int p = 0; p < 4; p++) { \
                mma_tf32(acc[mt][2 * p],     af[mt], &bf[p][0]); \
                mma_tf32(acc[mt][2 * p + 1], af[mt], &bf[p][2]); \
            } \
    } \
} while (0)

#define GEMM_MAINLOOP(NC) do { \
    FILL_ASYNC(0, 0); CPA_COMMIT(); \
    FILL_ASYNC(1, 1); CPA_COMMIT(); \
    FILL_ASYNC(2, 2); CPA_COMMIT(); \
    CPA_WAIT2(); __syncthreads(); \
    int sc_ = 0; \
    _Pragma("unroll 1") \
    for (int c = 0; c < (NC); ++c) { \
        const int cn_ = c + 3; \
        if (cn_ < (NC)) FILL_ASYNC(cn_, cn_ & 3); \
        CPA_COMMIT(); \
        COMPUTE(sc_); \
        CPA_WAIT2(); __syncthreads(); \
        sc_ = (sc_ + 1) & 3; \
    } \
} while (0)

// kernel 4: hdd[slot,:] = tf32( gelu( x[token,:] @ W1[e] + b1[e] ) )
__global__ __launch_bounds__(512) void gemm1_mma(
    const float* __restrict__ b1)
{
    const int e = blockIdx.z;
    const int count = g_counts[e];
    const int mtile = blockIdx.y * BM;
    if (mtile >= count) return;
    const int off = g_offsets[e];
    const int ntile = blockIdx.x * BN;

    GEMM_PROLOG3();

    const float* bscr = g_w1t + (size_t)(e * W1_NT + blockIdx.x) * W1_NC * 8192;
    const int m_a = mtile + frow;
    const bool aval = (m_a < count);
    const uint32_t aszf = aval ? 16u : 0u;
    const float* aptr = aval ? (g_xt + (size_t)g_tlist[e * NTOK + m_a] * HH) : g_xt;

    GEMM_MAINLOOP(W1_NC);

    const int lg = lane >> 2, lc = lane & 3;
#pragma unroll
    for (int nt = 0; nt < 8; nt++) {
        const int ncol = ntile + warpN * 64 + nt * 8 + lc * 2;
        const float2 bias = *(const float2*)(b1 + (size_t)e * FF + ncol);
#pragma unroll
        for (int mt = 0; mt < 2; mt++) {
            const int m0 = mtile + warpM * 32 + mt * 16 + lg;
            if (m0 < count) {
                float2 v;
                v.x = __uint_as_float(f2tf32(gelu_tanh(acc[mt][nt][0] + bias.x)));
                v.y = __uint_as_float(f2tf32(gelu_tanh(acc[mt][nt][1] + bias.y)));
                *(float2*)(g_hdd + (size_t)(off + m0) * FF + ncol) = v;
            }
            const int m1 = m0 + 8;
            if (m1 < count) {
                float2 v;
                v.x = __uint_as_float(f2tf32(gelu_tanh(acc[mt][nt][2] + bias.x)));
                v.y = __uint_as_float(f2tf32(gelu_tanh(acc[mt][nt][3] + bias.y)));
                *(float2*)(g_hdd + (size_t)(off + m1) * FF + ncol) = v;
            }
        }
    }
}

// kernel 5: out[token,:] += gate * ( hdd[slot,:] @ W2[e] + b2[e] )
__global__ __launch_bounds__(512) void gemm2_mma(
    const float* __restrict__ b2, float* __restrict__ out)
{
    const int e = blockIdx.z;
    const int count = g_counts[e];
    const int mtile = blockIdx.y * BM;
    if (mtile >= count) return;
    const int off = g_offsets[e];
    const int ntile = blockIdx.x * BN;

    GEMM_PROLOG3();

    const float* bscr = g_w2t + (size_t)(e * W2_NT + blockIdx.x) * W2_NC * 8192;
    const int m_a = mtile + frow;
    const bool aval = (m_a < count);
    const uint32_t aszf = aval ? 16u : 0u;
    const float* aptr = g_hdd + (size_t)(off + (aval ? m_a : 0)) * FF;

    GEMM_MAINLOOP(W2_NC);

    const int lg = lane >> 2, lc = lane & 3;
#pragma unroll
    for (int mt = 0; mt < 2; mt++) {
#pragma unroll
        for (int half = 0; half < 2; half++) {
            const int m = mtile + warpM * 32 + mt * 16 + lg + half * 8;
            if (m >= count) continue;
            const int tok = g_tlist[e * NTOK + m];
            const float g = g_glist[e * NTOK + m];
            float* dst = out + (size_t)tok * HH + ntile;
            const float* b2r = b2 + (size_t)e * HH + ntile;
#pragma unroll
            for (int nt = 0; nt < 8; nt++) {
                const int ncol = warpN * 64 + nt * 8 + lc * 2;
                atomicAdd(dst + ncol,     g * (acc[mt][nt][half * 2]     + b2r[ncol]));
                atomicAdd(dst + ncol + 1, g * (acc[mt][nt][half * 2 + 1] + b2r[ncol + 1]));
            }
        }
    }
}

// ---------------- launcher ------------------------------------------------------
extern "C" void kernel_launch(void* const* d_in, const int* in_sizes, int n_in,
                              void* d_out, int out_size)
{
    const float* x  = (const float*)d_in[0];
    const float* Wg = (const float*)d_in[1];
    const float* W1 = (const float*)d_in[2];
    const float* b1 = (const float*)d_in[3];
    const float* W2 = (const float*)d_in[4];
    const float* b2 = (const float*)d_in[5];
    float* out = (float*)d_out;

    cudaFuncSetAttribute(gemm1_mma, cudaFuncAttributeMaxDynamicSharedMemorySize, SMEM_DYN);
    cudaFuncSetAttribute(gemm2_mma, cudaFuncAttributeMaxDynamicSharedMemorySize, SMEM_DYN);

    float* w1t; cudaGetSymbolAddress((void**)&w1t, g_w1t);
    float* w2t; cudaGetSymbolAddress((void**)&w2t, g_w2t);

    prep_zero_x<<<1024, 256>>>(x, out);
    prep_w<<<EE * W1_NT * W1_NC, 256>>>(W1, w1t, HH, FF);
    prep_w<<<EE * W2_NT * W2_NC, 256>>>(W2, w2t, FF, HH);
    router_kernel<<<NTOK / 8, 256>>>(x, Wg);
    offsets_kernel<<<1, 32>>>();
    gemm1_mma<<<dim3(FF / BN, NTOK / BM, EE), 512, SMEM_DYN>>>(b1);
    gemm2_mma<<<dim3(HH / BN, NTOK / BM, EE), 512, SMEM_DYN>>>(b2, out);
}